// round 17
// baseline (speedup 1.0000x reference)
#include <cuda_runtime.h>
#include <float.h>

#define N_REF   500000
#define N_PC    128
#define N_FEAT  2000
#define TOP_K   16

#define BLOCKS           592
#define THREADS          256
#define WARPS_PER_BLOCK  (THREADS / 32)
#define TOTAL_WARPS      (BLOCKS * WARPS_PER_BLOCK)   // 4736
#define N_CAND           (BLOCKS * TOP_K)             // 9472
#define CAND_ROUNDS      (N_CAND / THREADS)           // 37 exactly

#define PROJ_BLOCKS      50
#define FEAT_PER_BLOCK   (N_FEAT / PROJ_BLOCKS)       // 40
#define PROJ_Y           4
#define FEAT_PER_Y       (FEAT_PER_BLOCK / PROJ_Y)    // 10

#define SURV_CAP         1024

// Scratch (no cudaMalloc allowed)
__device__ float g_qpart[PROJ_BLOCKS * N_PC];
__device__ float g_cand_d[N_CAND];
__device__ int   g_cand_i[N_CAND];
__device__ float g_bmin[BLOCKS];      // per-block minimum (compact, coalesced)
__device__ int   g_tix;               // completion ticket; reset by last block

// ---------------------------------------------------------------------------
// Warp-distributed top-16 insert. Lane l (<16) holds the l-th smallest
// (dval, divx). v must be warp-uniform. ~7 instructions, no serial chain.
// ---------------------------------------------------------------------------
__device__ __forceinline__ void warp_insert16(float& dval, int& divx,
                                              float& kmax, int lane,
                                              float v, int id) {
    unsigned m = __ballot_sync(0xFFFFFFFFu, dval < v);
    int pos = __popc(m & 0xFFFFu);
    float up_d = __shfl_up_sync(0xFFFFFFFFu, dval, 1);
    int   up_i = __shfl_up_sync(0xFFFFFFFFu, divx, 1);
    if (lane >= pos) {
        dval = (lane == pos) ? v  : up_d;
        divx = (lane == pos) ? id : up_i;
    }
    kmax = __shfl_sync(0xFFFFFFFFu, dval, 15);
}

// ---------------------------------------------------------------------------
// Warp bitonic sort of 32 floats (ascending by lane), values only.
// ---------------------------------------------------------------------------
__device__ __forceinline__ void bitonic32v(float& v, int lane) {
    #pragma unroll
    for (int k = 2; k <= 32; k <<= 1) {
        #pragma unroll
        for (int j = k >> 1; j > 0; j >>= 1) {
            float ov = __shfl_xor_sync(0xFFFFFFFFu, v, j);
            bool up      = ((lane & k) == 0);
            bool lower   = ((lane & j) == 0);
            bool takeMin = (lower == up);
            bool sel = takeMin ? (ov < v) : (ov > v);
            v = sel ? ov : v;
        }
    }
}

// Bitonic MERGE of a 32-lane bitonic sequence -> ascending (5 stages).
__device__ __forceinline__ void bitonic_merge32(float& v, int lane) {
    #pragma unroll
    for (int j = 16; j > 0; j >>= 1) {
        float ov = __shfl_xor_sync(0xFFFFFFFFu, v, j);
        v = ((lane & j) == 0) ? fminf(v, ov) : fmaxf(v, ov);
    }
}

// ---------------------------------------------------------------------------
// Kernel A (UNCHANGED from R14 best): partial query projection.
// 50 blocks x (128,4); block b covers 40 features, 10 per y-slice.
// ---------------------------------------------------------------------------
__global__ void __launch_bounds__(N_PC * PROJ_Y)
project_partial(const float* __restrict__ data_in,
                const float* __restrict__ tmat) {
    const int j  = threadIdx.x;          // 0..127 (PC index)
    const int y  = threadIdx.y;          // 0..3
    const int b  = blockIdx.x;
    const int k0 = b * FEAT_PER_BLOCK + y * FEAT_PER_Y;

    float acc = 0.0f;
    #pragma unroll
    for (int k = k0; k < k0 + FEAT_PER_Y; k++)
        acc += data_in[k] * tmat[k * N_PC + j];   // coalesced over j

    __shared__ float sred[PROJ_Y][N_PC];
    sred[y][j] = acc;
    __syncthreads();
    if (y == 0)
        g_qpart[b * N_PC + j] = sred[0][j] + sred[1][j] + sred[2][j] + sred[3][j];
}

// ---------------------------------------------------------------------------
// Kernel B (FUSED dist + final merge):
//   [prologue] reduce 50 projection partials -> shared query (R14).
//   [mainloop] warp/row, 4-row unroll, register double-buffer prefetch,
//     warp-distributed top-16 (byte-identical to R11..R14 best).
//   [tail] parallel rank-select block top-16 -> g_cand (sorted), g_bmin.
//   [ticket] threadfence + atomicAdd; LAST block finishes:
//     tau' = 16th smallest of 256 per-thread min-of-3 over the 592 block
//     minima (provable upper bound on the global 16th-smallest: the 16
//     smallest per-thread minima are 16 distinct candidates <= tau').
//     Threshold-scan all 9472 candidates (37 rounds, chunked loads MLP=8),
//     warp-aggregated append (~40-80 survivors), strided rank-select with
//     slot tie-break (deterministic), gather psuedo, mean -> out.
// ---------------------------------------------------------------------------
__global__ void __launch_bounds__(THREADS)
dist_topk_kernel(const float* __restrict__ ref,
                 const float* __restrict__ psuedo,
                 float* __restrict__ out) {
    const int tid  = threadIdx.x;
    const int lane = tid & 31;
    const int wid  = tid >> 5;
    const int gw   = blockIdx.x * WARPS_PER_BLOCK + wid;

    // ---- prologue: finish query projection into shared ----
    __shared__ __align__(16) float sq[N_PC];
    if (tid < N_PC) {
        float acc = 0.0f;
        #pragma unroll
        for (int b = 0; b < PROJ_BLOCKS; b++)
            acc += g_qpart[b * N_PC + tid];
        sq[tid] = acc;
    }
    __syncthreads();
    const float4 q = reinterpret_cast<const float4*>(sq)[lane];

    const int chunk = (N_REF + TOTAL_WARPS - 1) / TOTAL_WARPS;  // 106
    int start = gw * chunk;
    int end   = start + chunk;
    if (start > N_REF) start = N_REF;
    if (end   > N_REF) end   = N_REF;

    float dval = FLT_MAX;
    int   divx = 0;
    float kmax = FLT_MAX;

    const float4* __restrict__ ref4 = reinterpret_cast<const float4*>(ref);

    const int nIter = (end - start) / 4;
    int r = start;

    float4 A0, A1, A2, A3;
    if (nIter > 0) {
        A0 = __ldcs(ref4 + (size_t)(r + 0) * (N_PC / 4) + lane);
        A1 = __ldcs(ref4 + (size_t)(r + 1) * (N_PC / 4) + lane);
        A2 = __ldcs(ref4 + (size_t)(r + 2) * (N_PC / 4) + lane);
        A3 = __ldcs(ref4 + (size_t)(r + 3) * (N_PC / 4) + lane);
    }

    for (int it = 0; it < nIter; it++) {
        float4 B0, B1, B2, B3;
        if (it + 1 < nIter) {
            int rn = r + 4;
            B0 = __ldcs(ref4 + (size_t)(rn + 0) * (N_PC / 4) + lane);
            B1 = __ldcs(ref4 + (size_t)(rn + 1) * (N_PC / 4) + lane);
            B2 = __ldcs(ref4 + (size_t)(rn + 2) * (N_PC / 4) + lane);
            B3 = __ldcs(ref4 + (size_t)(rn + 3) * (N_PC / 4) + lane);
        }

        float s0 = fabsf(A0.x - q.x) + fabsf(A0.y - q.y) + fabsf(A0.z - q.z) + fabsf(A0.w - q.w);
        float s1 = fabsf(A1.x - q.x) + fabsf(A1.y - q.y) + fabsf(A1.z - q.z) + fabsf(A1.w - q.w);
        float s2 = fabsf(A2.x - q.x) + fabsf(A2.y - q.y) + fabsf(A2.z - q.z) + fabsf(A2.w - q.w);
        float s3 = fabsf(A3.x - q.x) + fabsf(A3.y - q.y) + fabsf(A3.z - q.z) + fabsf(A3.w - q.w);

        #pragma unroll
        for (int off = 16; off > 0; off >>= 1) {
            s0 += __shfl_xor_sync(0xFFFFFFFFu, s0, off);
            s1 += __shfl_xor_sync(0xFFFFFFFFu, s1, off);
            s2 += __shfl_xor_sync(0xFFFFFFFFu, s2, off);
            s3 += __shfl_xor_sync(0xFFFFFFFFu, s3, off);
        }
        if (s0 < kmax) warp_insert16(dval, divx, kmax, lane, s0, r + 0);
        if (s1 < kmax) warp_insert16(dval, divx, kmax, lane, s1, r + 1);
        if (s2 < kmax) warp_insert16(dval, divx, kmax, lane, s2, r + 2);
        if (s3 < kmax) warp_insert16(dval, divx, kmax, lane, s3, r + 3);

        A0 = B0; A1 = B1; A2 = B2; A3 = B3;
        r += 4;
    }
    for (; r < end; r++) {
        float4 a0 = __ldcs(ref4 + (size_t)r * (N_PC / 4) + lane);
        float s0 = fabsf(a0.x - q.x) + fabsf(a0.y - q.y) + fabsf(a0.z - q.z) + fabsf(a0.w - q.w);
        #pragma unroll
        for (int off = 16; off > 0; off >>= 1)
            s0 += __shfl_xor_sync(0xFFFFFFFFu, s0, off);
        if (s0 < kmax) warp_insert16(dval, divx, kmax, lane, s0, r);
    }

    // ---- tail: parallel rank-select block top-16 ----
    __shared__ float sbd[WARPS_PER_BLOCK * TOP_K];   // 128
    __shared__ int   sbi[WARPS_PER_BLOCK * TOP_K];
    if (lane < TOP_K) {
        sbd[wid * TOP_K + lane] = dval;
        sbi[wid * TOP_K + lane] = divx;
    }
    __syncthreads();

    if (tid < 128) {
        float v  = sbd[tid];
        int   id = sbi[tid];
        int rank = 0;
        #pragma unroll 8
        for (int j = 0; j < 128; j++) {
            float o = sbd[j];
            rank += (o < v) || (o == v && j < tid);
        }
        if (rank < TOP_K) {
            g_cand_d[blockIdx.x * TOP_K + rank] = v;
            g_cand_i[blockIdx.x * TOP_K + rank] = id;
        }
        if (rank == 0) g_bmin[blockIdx.x] = v;
    }

    // ---- ticket: last block to finish performs the final merge ----
    __threadfence();                     // release candidate writes
    __syncthreads();
    __shared__ int s_last;
    if (tid == 0) {
        int t = atomicAdd(&g_tix, 1);
        s_last = (t == BLOCKS - 1) ? 1 : 0;
        if (s_last) g_tix = 0;           // reset for graph replay
    }
    __syncthreads();
    if (!s_last) return;
    __threadfence();                     // acquire all blocks' writes

    // ======================= final merge (last block) =======================
    __shared__ float m_a[WARPS_PER_BLOCK * TOP_K];   // 128
    __shared__ float m_b[WARPS_PER_BLOCK * TOP_K];
    __shared__ int   s_cnt;
    __shared__ float s_d[SURV_CAP];
    __shared__ int   s_c[SURV_CAP];
    __shared__ float s_sel[TOP_K];

    if (tid == 0) s_cnt = 0;

    // tau': per-thread min of 3 block minima (coalesced), then exact 16th of
    // the 256 per-thread minima via bitonic sort + merge tree (8 -> 1 lists).
    float v0 = g_bmin[tid];                                    // 0..255
    float v1 = g_bmin[tid + 256];                              // 256..511
    float v2 = (tid + 512 < BLOCKS) ? g_bmin[tid + 512] : FLT_MAX;
    float mv = fminf(v0, fminf(v1, v2));
    bitonic32v(mv, lane);
    if (lane < TOP_K) m_a[wid * TOP_K + lane] = mv;
    __syncthreads();

    {
        float* src = m_a;
        float* dst = m_b;
        int n = WARPS_PER_BLOCK;    // 8 -> 4 -> 2 -> 1
        while (n > 1) {
            int half = n >> 1;
            if (wid < half) {
                float v = (lane < TOP_K)
                        ? src[(2 * wid) * TOP_K + lane]
                        : src[(2 * wid + 1) * TOP_K + (31 - lane)];
                bitonic_merge32(v, lane);
                if (lane < TOP_K) dst[wid * TOP_K + lane] = v;
            }
            __syncthreads();
            n = half;
            float* tmp = src; src = dst; dst = tmp;
        }
        if (tid == 0) s_sel[0] = src[TOP_K - 1];   // stash tau'
    }
    __syncthreads();
    const float tau = s_sel[0];

    // threshold scan of all candidates: 37 rounds, chunked loads (MLP=8)
    for (int base = 0; base < CAND_ROUNDS; base += 8) {
        float vb[8];
        #pragma unroll
        for (int j = 0; j < 8; j++) {
            int k = base + j;
            vb[j] = (k < CAND_ROUNDS) ? g_cand_d[tid + k * THREADS] : FLT_MAX;
        }
        #pragma unroll
        for (int j = 0; j < 8; j++) {
            int k = base + j;
            int c = tid + k * THREADS;
            bool pred = (k < CAND_ROUNDS) && (vb[j] <= tau);
            unsigned m = __ballot_sync(0xFFFFFFFFu, pred);
            if (m) {
                int bpos = 0;
                if (lane == 0) bpos = atomicAdd(&s_cnt, __popc(m));
                bpos = __shfl_sync(0xFFFFFFFFu, bpos, 0);
                if (pred) {
                    int pos = bpos + __popc(m & ((1u << lane) - 1u));
                    if (pos < SURV_CAP) {
                        s_d[pos] = vb[j];
                        s_c[pos] = c;
                    }
                }
            }
        }
    }
    __syncthreads();
    const int cnt = (s_cnt < SURV_CAP) ? s_cnt : SURV_CAP;

    // rank-select top-16 of survivors (strided; slot tie-break), gather, mean
    for (int s = tid; s < cnt; s += THREADS) {
        float v = s_d[s];
        int   c = s_c[s];
        int rank = 0;
        for (int j = 0; j < cnt; j++) {
            float o = s_d[j];
            rank += (o < v) || (o == v && s_c[j] < c);
        }
        if (rank < TOP_K) s_sel[rank] = psuedo[g_cand_i[c]];
    }
    __syncthreads();

    if (tid < 32) {
        float v = (tid < TOP_K) ? s_sel[tid] : 0.0f;
        #pragma unroll
        for (int off = 16; off > 0; off >>= 1)
            v += __shfl_xor_sync(0xFFFFFFFFu, v, off);
        if (tid == 0) out[0] = v * (1.0f / TOP_K);
    }
}

// ---------------------------------------------------------------------------
// Launch (2 kernels)
// ---------------------------------------------------------------------------
extern "C" void kernel_launch(void* const* d_in, const int* in_sizes, int n_in,
                              void* d_out, int out_size) {
    const float* data_in = (const float*)d_in[0];
    const float* tmat    = (const float*)d_in[1];
    const float* ref     = (const float*)d_in[2];
    const float* psuedo  = (const float*)d_in[3];
    float* out = (float*)d_out;

    dim3 pb(N_PC, PROJ_Y);
    project_partial<<<PROJ_BLOCKS, pb>>>(data_in, tmat);
    dist_topk_kernel<<<BLOCKS, THREADS>>>(ref, psuedo, out);
}